// round 5
// baseline (speedup 1.0000x reference)
#include <cuda_runtime.h>
#include <math.h>

#define BB 8
#define CC 64
#define NN 4096
#define TOT (BB*CC*NN)
#define TILE_N 128
#define NBLK 32              // n-tiles per batch
#define TILES (BB*NBLK)      // 256
#define GRID 296             // 2 CTAs per SM on 148 SMs (co-resident)
#define NTHREADS 256

typedef unsigned long long u64;

// Scratch (allocation-free: __device__ globals)
__device__ float g_z[TOT];                   // z = W @ x (8 MB)
__device__ float g_psum[BB*CC*NBLK];         // partial Σz   [b][o][nb]
__device__ float g_psq [BB*CC*NBLK];         // partial Σz²  [b][o][nb]
__device__ float g_spart[TILES];             // partial s_b per tile
__device__ float g_scale[BB*CC];
__device__ float g_bias [BB*CC];
__device__ unsigned int g_bar = 0;           // monotonic grid barrier
__device__ unsigned int g_ticket = 0;        // tile ticket (reset each launch)

// ---- f32x2 packed helpers (sm_103a) ----
__device__ __forceinline__ u64 ffma2(u64 a, u64 b, u64 c) {
    u64 d;
    asm("fma.rn.f32x2 %0, %1, %2, %3;" : "=l"(d) : "l"(a), "l"(b), "l"(c));
    return d;
}
__device__ __forceinline__ u64 packdup(float v) {
    u64 r;
    asm("mov.b64 %0, {%1, %2};" : "=l"(r) : "f"(v), "f"(v));
    return r;
}
__device__ __forceinline__ void unpack2(u64 v, float& lo, float& hi) {
    asm("mov.b64 {%0, %1}, %2;" : "=f"(lo), "=f"(hi) : "l"(v));
}

// Replay-safe grid barrier: monotonic counter, target = next multiple of GRID.
__device__ __forceinline__ void grid_barrier() {
    __syncthreads();
    if (threadIdx.x == 0) {
        __threadfence();
        unsigned int arrive = atomicAdd(&g_bar, 1u) + 1u;
        unsigned int target = ((arrive - 1u) / GRID + 1u) * GRID;
        for (;;) {
            unsigned int v;
            asm volatile("ld.acquire.gpu.u32 %0, [%1];" : "=r"(v) : "l"(&g_bar));
            if ((int)(v - target) >= 0) break;
            __nanosleep(64);
        }
    }
    __syncthreads();
}

__global__ __launch_bounds__(NTHREADS, 2)
void fused_kernel(const float* __restrict__ x,
                  const float* __restrict__ wvec,
                  const float* __restrict__ W,
                  const float* __restrict__ conv_b,
                  const float* __restrict__ gamma,
                  const float* __restrict__ beta,
                  float* __restrict__ out)
{
    extern __shared__ char smem_raw[];
    u64*   wt2 = (u64*)smem_raw;                 // [64][64] dup pairs (32 KB)
    float* xs  = (float*)(smem_raw + 32768);     // [64][128]           (32 KB)
    __shared__ float sred[4];
    __shared__ int   s_tile;
    __shared__ float zZ[BB*CC], zQ[BB*CC], s_sh[BB];

    const int t  = threadIdx.x;
    const int tx = t & 15, ty = t >> 4;

    // ---- Build dup-packed W once per block: wt2[c][o] = {W[o,c], W[o,c]} ----
    #pragma unroll
    for (int i = 0; i < 16; i++) {
        int idx = i * 256 + t;
        float v = W[idx];
        wt2[(idx & 63) * 64 + (idx >> 6)] = packdup(v);
    }
    // (visibility covered by the post-load __syncthreads in the tile loop)

    // ================= GEMM + stats phase (ticket-scheduled tiles) =========
    for (;;) {
        if (t == 0) s_tile = (int)atomicAdd(&g_ticket, 1u);
        __syncthreads();                       // also fences xs reuse
        const int tile = s_tile;
        if (tile >= TILES) break;
        const int b  = tile >> 5;
        const int nb = tile & 31;
        const int n0 = nb * TILE_N;

        // tanh(w)² partial for this 128-wide n-slice (warps 0-3)
        if (t < 128) {
            float vv = tanhf(wvec[b * NN + n0 + t]);
            vv = fmaxf(vv, 0.f);
            float sp = vv * vv;
            #pragma unroll
            for (int off = 16; off > 0; off >>= 1)
                sp += __shfl_xor_sync(0xFFFFFFFFu, sp, off);
            if ((t & 31) == 0) sred[t >> 5] = sp;
        }

        // Load x tile: 64 c-rows × 32 float4
        const float4* x4 = (const float4*)(x + ((size_t)b * CC) * NN + n0);
        #pragma unroll
        for (int i = 0; i < 8; i++) {
            int idx = i * 256 + t;
            int c = idx >> 5, j = idx & 31;
            ((float4*)(xs + c * 128))[j] = x4[c * (NN / 4) + j];
        }
        __syncthreads();
        if (t == 0) g_spart[tile] = (sred[0] + sred[1]) + (sred[2] + sred[3]);

        // 4o × 8n microtile, FFMA2 over packed n-pairs
        u64 acc[4][4];
        #pragma unroll
        for (int i = 0; i < 4; i++)
            #pragma unroll
            for (int j = 0; j < 4; j++) acc[i][j] = 0ull;

        #pragma unroll 16
        for (int c = 0; c < 64; c++) {
            ulonglong2 w01 = *(const ulonglong2*)(wt2 + c * 64 + ty * 4);
            ulonglong2 w23 = *(const ulonglong2*)(wt2 + c * 64 + ty * 4 + 2);
            ulonglong2 xa  = *(const ulonglong2*)(xs + c * 128 + tx * 8);
            ulonglong2 xb  = *(const ulonglong2*)(xs + c * 128 + tx * 8 + 4);
            acc[0][0] = ffma2(w01.x, xa.x, acc[0][0]);
            acc[0][1] = ffma2(w01.x, xa.y, acc[0][1]);
            acc[0][2] = ffma2(w01.x, xb.x, acc[0][2]);
            acc[0][3] = ffma2(w01.x, xb.y, acc[0][3]);
            acc[1][0] = ffma2(w01.y, xa.x, acc[1][0]);
            acc[1][1] = ffma2(w01.y, xa.y, acc[1][1]);
            acc[1][2] = ffma2(w01.y, xb.x, acc[1][2]);
            acc[1][3] = ffma2(w01.y, xb.y, acc[1][3]);
            acc[2][0] = ffma2(w23.x, xa.x, acc[2][0]);
            acc[2][1] = ffma2(w23.x, xa.y, acc[2][1]);
            acc[2][2] = ffma2(w23.x, xb.x, acc[2][2]);
            acc[2][3] = ffma2(w23.x, xb.y, acc[2][3]);
            acc[3][0] = ffma2(w23.y, xa.x, acc[3][0]);
            acc[3][1] = ffma2(w23.y, xa.y, acc[3][1]);
            acc[3][2] = ffma2(w23.y, xb.x, acc[3][2]);
            acc[3][3] = ffma2(w23.y, xb.y, acc[3][3]);
        }

        // Write z directly from packed pairs (n-consecutive layout)
        float* zp = g_z + ((size_t)b * CC) * NN + n0 + tx * 8;
        #pragma unroll
        for (int i = 0; i < 4; i++) {
            int o = ty * 4 + i;
            ulonglong2 p0; p0.x = acc[i][0]; p0.y = acc[i][1];
            ulonglong2 p1; p1.x = acc[i][2]; p1.y = acc[i][3];
            *(ulonglong2*)(zp + (size_t)o * NN)     = p0;
            *(ulonglong2*)(zp + (size_t)o * NN + 4) = p1;
        }

        // Per-thread stats then reduce across 16 tx lanes (stays in half-warp)
        float lsum[4], lsq[4];
        #pragma unroll
        for (int i = 0; i < 4; i++) {
            float v0, v1, v2, v3, v4, v5, v6, v7;
            unpack2(acc[i][0], v0, v1);
            unpack2(acc[i][1], v2, v3);
            unpack2(acc[i][2], v4, v5);
            unpack2(acc[i][3], v6, v7);
            lsum[i] = ((v0 + v1) + (v2 + v3)) + ((v4 + v5) + (v6 + v7));
            lsq[i]  = fmaf(v0, v0, fmaf(v1, v1, fmaf(v2, v2, fmaf(v3, v3,
                      fmaf(v4, v4, fmaf(v5, v5, fmaf(v6, v6, v7 * v7)))))));
        }
        #pragma unroll
        for (int off = 8; off > 0; off >>= 1) {
            #pragma unroll
            for (int i = 0; i < 4; i++) {
                lsum[i] += __shfl_xor_sync(0xFFFFFFFFu, lsum[i], off);
                lsq[i]  += __shfl_xor_sync(0xFFFFFFFFu, lsq[i],  off);
            }
        }
        if (tx == 0) {
            #pragma unroll
            for (int i = 0; i < 4; i++) {
                int o = ty * 4 + i;
                g_psum[(b * CC + o) * NBLK + nb] = lsum[i];
                g_psq [(b * CC + o) * NBLK + nb] = lsq[i];
            }
        }
    }

    // ================= barrier 1: all stats + z visible =====================
    grid_barrier();

    // ================= finalize (block 0 only) ==============================
    if (blockIdx.x == 0) {
        const int w = t >> 5, l = t & 31;
        // s_b: warp w reduces batch w's 32 tile partials
        {
            float sp = g_spart[w * NBLK + l];
            #pragma unroll
            for (int off = 16; off > 0; off >>= 1)
                sp += __shfl_xor_sync(0xFFFFFFFFu, sp, off);
            if (l == 0) s_sh[w] = sp;
        }
        // Z,Q: each thread reduces 2 (b,o) rows of 32 contiguous partials
        #pragma unroll
        for (int k = 0; k < 2; k++) {
            int bo = t + k * 256;
            const float4* p4 = (const float4*)(g_psum + bo * NBLK);
            const float4* q4 = (const float4*)(g_psq  + bo * NBLK);
            float Z = 0.f, Q = 0.f;
            #pragma unroll
            for (int i = 0; i < NBLK / 4; i++) {
                float4 a = p4[i], c = q4[i];
                Z += (a.x + a.y) + (a.z + a.w);
                Q += (c.x + c.y) + (c.z + c.w);
            }
            zZ[bo] = Z; zQ[bo] = Q;
        }
        __syncthreads();
        if (t < CC) {
            const int o = t;
            float cb = conv_b[o];
            float alpha[BB], offv[BB];
            float mean_acc = 0.f, sq_acc = 0.f;
            #pragma unroll
            for (int bb = 0; bb < BB; bb++) {
                float s = s_sh[bb];
                float a = 1.f / (1.f + (float)NN * s);
                float Z = zZ[bb * CC + o];
                float Q = zQ[bb * CC + o];
                float off = a * s * Z + cb;
                alpha[bb] = a; offv[bb] = off;
                mean_acc += a * Z + (float)NN * off;
                sq_acc   += a * a * Q + 2.f * a * off * Z + (float)NN * off * off;
            }
            const float inv_cnt = 1.f / (float)(BB * NN);
            float mean = mean_acc * inv_cnt;
            float var  = sq_acc * inv_cnt - mean * mean;
            float invstd = rsqrtf(var + 1e-5f);
            float g  = gamma[o] * invstd;
            float be = beta[o];
            #pragma unroll
            for (int bb = 0; bb < BB; bb++) {
                g_scale[bb * CC + o] = alpha[bb] * g;
                g_bias [bb * CC + o] = (offv[bb] - mean) * g + be;
            }
        }
    }

    // ================= barrier 2: scale/bias visible ========================
    grid_barrier();

    // ================= epilogue: out = relu(scale*z + bias) ================
    for (int r = blockIdx.x; r < BB * CC; r += GRID) {
        const float sc = g_scale[r];
        const float bi = g_bias[r];
        const float4* z4 = (const float4*)(g_z + (size_t)r * NN);
        float4* o4 = (float4*)(out + (size_t)r * NN);
        float4 v[4];
        #pragma unroll
        for (int i = 0; i < 4; i++) v[i] = z4[t + i * 256];
        #pragma unroll
        for (int i = 0; i < 4; i++) {
            float4 rr;
            rr.x = fmaxf(fmaf(sc, v[i].x, bi), 0.f);
            rr.y = fmaxf(fmaf(sc, v[i].y, bi), 0.f);
            rr.z = fmaxf(fmaf(sc, v[i].z, bi), 0.f);
            rr.w = fmaxf(fmaf(sc, v[i].w, bi), 0.f);
            o4[t + i * 256] = rr;
        }
    }

    // reset ticket for next launch (safe: all blocks past barrier 2)
    if (blockIdx.x == 0 && t == 0) g_ticket = 0;
}

extern "C" void kernel_launch(void* const* d_in, const int* in_sizes, int n_in,
                              void* d_out, int out_size) {
    const float* x      = (const float*)d_in[0];  // [8,64,4096,1]
    const float* w      = (const float*)d_in[1];  // [8,4096]
    const float* conv_w = (const float*)d_in[2];  // [64,64,1,1]
    const float* conv_b = (const float*)d_in[3];  // [64]
    const float* gamma  = (const float*)d_in[4];  // [64]
    const float* beta   = (const float*)d_in[5];  // [64]
    float* out = (float*)d_out;

    cudaFuncSetAttribute(fused_kernel,
                         cudaFuncAttributeMaxDynamicSharedMemorySize, 65536);
    fused_kernel<<<GRID, NTHREADS, 65536>>>(x, w, conv_w, conv_b, gamma, beta, out);
}

// round 6
// speedup vs baseline: 1.5023x; 1.5023x over previous
#include <cuda_runtime.h>
#include <math.h>

#define BB 8
#define CC 64
#define NN 4096
#define TOT (BB*CC*NN)
#define TILE_N 256
#define NTB (NN/TILE_N)      // 16 n-tiles per batch
#define TILES (BB*NTB)       // 128 blocks

typedef unsigned long long u64;

// Scratch (allocation-free: __device__ globals)
__device__ float g_z[TOT];                 // z = W @ x (8 MB)
__device__ float g_psum[BB*CC*NTB];        // partial Σz   [b][o][nb]
__device__ float g_psq [BB*CC*NTB];        // partial Σz²  [b][o][nb]
__device__ float g_spart[TILES];           // partial s_b  [b][nb]

// ---- f32x2 packed helpers (sm_103a) ----
__device__ __forceinline__ u64 ffma2(u64 a, u64 b, u64 c) {
    u64 d;
    asm("fma.rn.f32x2 %0, %1, %2, %3;" : "=l"(d) : "l"(a), "l"(b), "l"(c));
    return d;
}
__device__ __forceinline__ u64 packdup(float v) {
    u64 r;
    asm("mov.b64 %0, {%1, %2};" : "=l"(r) : "f"(v), "f"(v));
    return r;
}
__device__ __forceinline__ void unpack2(u64 v, float& lo, float& hi) {
    asm("mov.b64 {%0, %1}, %2;" : "=f"(lo), "=f"(hi) : "l"(v));
}

// ============================================================================
// K1: z[b,o,n] = Σ_c W[o,c]·x[b,c,n].  Tile 64o × 256n, 256 threads.
// Warp w owns o∈[8w,8w+8) -> W operands are BROADCAST LDS (cheap);
// lane owns 8 consecutive n -> 2 LDS.128 per c.  32 FFMA2/c/lane, FMA-bound.
// Emits z, per-tile Σz/Σz² partials, and the tanh(w)² partial for its slice.
// ============================================================================
__global__ __launch_bounds__(256, 1)
void k1_gemm(const float* __restrict__ x,
             const float* __restrict__ wvec,
             const float* __restrict__ W)
{
    extern __shared__ char sm[];
    u64*   wt2 = (u64*)sm;                  // [64][64]: wt2[c*64+o]=dup(W[o,c]) 32KB
    float* xs  = (float*)(sm + 32768);      // [64][256]  64KB
    __shared__ float sred[8];

    const int t    = threadIdx.x;
    const int tile = blockIdx.x;
    const int b    = tile >> 4;
    const int nb   = tile & 15;
    const int n0   = nb * TILE_N;

    // tanh(w)² partial: each thread one element of this 256-wide slice
    {
        float vv = tanhf(wvec[b * NN + n0 + t]);
        vv = fmaxf(vv, 0.f);
        float sp = vv * vv;
        #pragma unroll
        for (int off = 16; off > 0; off >>= 1)
            sp += __shfl_xor_sync(0xFFFFFFFFu, sp, off);
        if ((t & 31) == 0) sred[t >> 5] = sp;
    }

    // Load W dup-packed (transposed): wt2[c][o] = {W[o,c], W[o,c]}
    #pragma unroll
    for (int i = 0; i < 16; i++) {
        int idx = i * 256 + t;
        wt2[(idx & 63) * 64 + (idx >> 6)] = packdup(W[idx]);
    }
    // Load x tile: 64 c-rows × 64 float4
    const float4* x4 = (const float4*)(x + ((size_t)b * CC) * NN + n0);
    #pragma unroll
    for (int i = 0; i < 16; i++) {
        int idx = i * 256 + t;
        int c = idx >> 6, j = idx & 63;
        ((float4*)(xs + c * TILE_N))[j] = x4[c * (NN / 4) + j];
    }
    __syncthreads();
    if (t == 0) {
        float s = 0.f;
        #pragma unroll
        for (int i = 0; i < 8; i++) s += sred[i];
        g_spart[tile] = s;
    }

    const int wid = t >> 5, lane = t & 31;
    const int o0 = wid * 8;
    const float* xbase = xs + lane * 8;

    u64 acc[8][4];
    #pragma unroll
    for (int i = 0; i < 8; i++)
        #pragma unroll
        for (int j = 0; j < 4; j++) acc[i][j] = 0ull;

    #pragma unroll 2
    for (int c = 0; c < 64; c++) {
        const u64* wrow = wt2 + c * 64 + o0;
        ulonglong2 w01 = *(const ulonglong2*)(wrow);      // broadcast
        ulonglong2 w23 = *(const ulonglong2*)(wrow + 2);
        ulonglong2 w45 = *(const ulonglong2*)(wrow + 4);
        ulonglong2 w67 = *(const ulonglong2*)(wrow + 6);
        const float* xr = xbase + c * TILE_N;
        ulonglong2 xa = *(const ulonglong2*)(xr);         // n pairs 0-3
        ulonglong2 xb = *(const ulonglong2*)(xr + 4);     // n pairs 4-7
        u64 wv[8] = {w01.x, w01.y, w23.x, w23.y, w45.x, w45.y, w67.x, w67.y};
        #pragma unroll
        for (int i = 0; i < 8; i++) {
            acc[i][0] = ffma2(wv[i], xa.x, acc[i][0]);
            acc[i][1] = ffma2(wv[i], xa.y, acc[i][1]);
            acc[i][2] = ffma2(wv[i], xb.x, acc[i][2]);
            acc[i][3] = ffma2(wv[i], xb.y, acc[i][3]);
        }
    }

    // Write z + per-o stats (full-warp reduce over the 256 n's)
    #pragma unroll
    for (int i = 0; i < 8; i++) {
        const int o = o0 + i;
        float* zo = g_z + ((size_t)(b * CC + o)) * NN + n0 + lane * 8;
        ulonglong2 p0; p0.x = acc[i][0]; p0.y = acc[i][1];
        ulonglong2 p1; p1.x = acc[i][2]; p1.y = acc[i][3];
        *(ulonglong2*)(zo)     = p0;
        *(ulonglong2*)(zo + 4) = p1;

        float v0, v1, v2, v3, v4, v5, v6, v7;
        unpack2(acc[i][0], v0, v1);
        unpack2(acc[i][1], v2, v3);
        unpack2(acc[i][2], v4, v5);
        unpack2(acc[i][3], v6, v7);
        float s = ((v0 + v1) + (v2 + v3)) + ((v4 + v5) + (v6 + v7));
        float q = fmaf(v0, v0, fmaf(v1, v1, fmaf(v2, v2, fmaf(v3, v3,
                  fmaf(v4, v4, fmaf(v5, v5, fmaf(v6, v6, v7 * v7)))))));
        #pragma unroll
        for (int off = 16; off > 0; off >>= 1) {
            s += __shfl_xor_sync(0xFFFFFFFFu, s, off);
            q += __shfl_xor_sync(0xFFFFFFFFu, q, off);
        }
        if (lane == 0) {
            g_psum[(b * CC + o) * NTB + nb] = s;
            g_psq [(b * CC + o) * NTB + nb] = q;
        }
    }
}

// ============================================================================
// K3: one block per (b,o) row. Computes its own scale/bias from the partial
// arrays (tiny, L2-resident), then out = relu(scale*z + bias).
// ============================================================================
__global__ __launch_bounds__(256)
void k3_epilogue(const float* __restrict__ conv_b,
                 const float* __restrict__ gamma,
                 const float* __restrict__ beta,
                 float* __restrict__ out)
{
    const int row = blockIdx.x;              // b*64 + o
    const int b   = row >> 6;
    const int o   = row & 63;
    const int t   = threadIdx.x;

    __shared__ float s_sh[BB], Zs[BB], Qs[BB];
    __shared__ float sc_sh, bi_sh;

    if (t < 128) {
        const int bb = t >> 4, i = t & 15;   // groups of 16 lanes, warp-aligned
        float sp = g_spart[bb * NTB + i];
        float Z  = g_psum[(bb * CC + o) * NTB + i];
        float Q  = g_psq [(bb * CC + o) * NTB + i];
        #pragma unroll
        for (int off = 8; off > 0; off >>= 1) {
            sp += __shfl_xor_sync(0xFFFFFFFFu, sp, off);
            Z  += __shfl_xor_sync(0xFFFFFFFFu, Z,  off);
            Q  += __shfl_xor_sync(0xFFFFFFFFu, Q,  off);
        }
        if (i == 0) { s_sh[bb] = sp; Zs[bb] = Z; Qs[bb] = Q; }
    }
    __syncthreads();

    if (t == 0) {
        const float cb = conv_b[o];
        float alpha_b = 0.f, off_b = 0.f;
        float mean_acc = 0.f, sq_acc = 0.f;
        #pragma unroll
        for (int bb = 0; bb < BB; bb++) {
            float s = s_sh[bb];
            float a = 1.f / (1.f + (float)NN * s);
            float Z = Zs[bb];
            float Q = Qs[bb];
            float off = a * s * Z + cb;
            if (bb == b) { alpha_b = a; off_b = off; }
            mean_acc += a * Z + (float)NN * off;
            sq_acc   += a * a * Q + 2.f * a * off * Z + (float)NN * off * off;
        }
        const float inv_cnt = 1.f / (float)(BB * NN);
        float mean = mean_acc * inv_cnt;
        float var  = sq_acc * inv_cnt - mean * mean;
        float invstd = rsqrtf(var + 1e-5f);
        float g = gamma[o] * invstd;
        sc_sh = alpha_b * g;
        bi_sh = (off_b - mean) * g + beta[o];
    }
    __syncthreads();

    const float sc = sc_sh, bi = bi_sh;
    const float4* z4 = (const float4*)(g_z + (size_t)row * NN);
    float4* o4 = (float4*)(out + (size_t)row * NN);
    float4 v[4];
    #pragma unroll
    for (int i = 0; i < 4; i++) v[i] = z4[t + i * 256];
    #pragma unroll
    for (int i = 0; i < 4; i++) {
        float4 r;
        r.x = fmaxf(fmaf(sc, v[i].x, bi), 0.f);
        r.y = fmaxf(fmaf(sc, v[i].y, bi), 0.f);
        r.z = fmaxf(fmaf(sc, v[i].z, bi), 0.f);
        r.w = fmaxf(fmaf(sc, v[i].w, bi), 0.f);
        o4[t + i * 256] = r;
    }
}

extern "C" void kernel_launch(void* const* d_in, const int* in_sizes, int n_in,
                              void* d_out, int out_size) {
    const float* x      = (const float*)d_in[0];  // [8,64,4096,1]
    const float* w      = (const float*)d_in[1];  // [8,4096]
    const float* conv_w = (const float*)d_in[2];  // [64,64,1,1]
    const float* conv_b = (const float*)d_in[3];  // [64]
    const float* gamma  = (const float*)d_in[4];  // [64]
    const float* beta   = (const float*)d_in[5];  // [64]
    float* out = (float*)d_out;

    cudaFuncSetAttribute(k1_gemm,
                         cudaFuncAttributeMaxDynamicSharedMemorySize, 98304);
    k1_gemm<<<TILES, 256, 98304>>>(x, w, conv_w);
    k3_epilogue<<<BB * CC, 256>>>(conv_b, gamma, beta, out);
}